// round 15
// baseline (speedup 1.0000x reference)
#include <cuda_runtime.h>
#include <cstdint>

// Problem constants
#define N_NODES  8192
#define CH       128
#define NEXP     64
#define NODES_PER_CHUNK 32              // nodes per GEMM CTA (2 subtiles of 16)
#define SUBN     16
#define MAX_PAD  10240                  // 8192 + 64*32
#define MAX_CHK  320                    // MAX_PAD / 32

// B (resident, 32-float k-tile layout)
#define B_ROW     144                   // 32 words + 16B pad
#define B_KTILE   (128 * B_ROW)         // 18432
#define B_BYTES   (4 * B_KTILE)         // 73728
// A (streamed, 16-float tiles, 4-stage ring)
#define A_ROW     80                    // 16 words + 16B pad (conflict-free)
#define A_TILE    (128 * A_ROW)         // 10240
#define A_NSTAGES 4
#define A_OFF     B_BYTES
#define SMEM_NODE (A_OFF + A_NSTAGES * A_TILE)   // 114688
#define SMEM_TOTAL (SMEM_NODE + 128)

// Scratch
__device__ int   g_sorted[MAX_PAD];
__device__ int   g_chunk_expert[MAX_CHK];
__device__ float g_Wr[NEXP * CH * CH];  // tf32-rounded W

// ---------------------------------------------------------------------------
// helpers
// ---------------------------------------------------------------------------
__device__ __forceinline__ uint32_t smem_u32(const void* p) {
    uint32_t a;
    asm("{ .reg .u64 t; cvta.to.shared.u64 t, %1; cvt.u32.u64 %0, t; }"
        : "=r"(a) : "l"(p));
    return a;
}

__device__ __forceinline__ uint32_t f2tf32(float f) {
    uint32_t u;
    asm("cvt.rna.tf32.f32 %0, %1;" : "=r"(u) : "f"(f));
    return u;
}

__device__ __forceinline__ void cp16(uint32_t dst, const void* src, int sz) {
    asm volatile("cp.async.cg.shared.global [%0], [%1], 16, %2;"
                 :: "r"(dst), "l"(src), "r"(sz) : "memory");
}
__device__ __forceinline__ void cp_commit() {
    asm volatile("cp.async.commit_group;" ::: "memory");
}
template <int N>
__device__ __forceinline__ void cp_wait() {
    asm volatile("cp.async.wait_group %0;" :: "n"(N) : "memory");
}

__device__ __forceinline__ void ldsm_x4(uint32_t* r, uint32_t addr) {
    asm volatile("ldmatrix.sync.aligned.m8n8.x4.shared.b16 {%0,%1,%2,%3}, [%4];"
                 : "=r"(r[0]), "=r"(r[1]), "=r"(r[2]), "=r"(r[3])
                 : "r"(addr));
}

__device__ __forceinline__ void mma_tf32(float* d, const uint32_t* a, const uint32_t* b) {
    asm volatile(
        "mma.sync.aligned.m16n8k8.row.col.f32.tf32.tf32.f32 "
        "{%0,%1,%2,%3}, {%4,%5,%6,%7}, {%8,%9}, {%0,%1,%2,%3};\n"
        : "+f"(d[0]), "+f"(d[1]), "+f"(d[2]), "+f"(d[3])
        : "r"(a[0]), "r"(a[1]), "r"(a[2]), "r"(a[3]),
          "r"(b[0]), "r"(b[1]));
}

// ---------------------------------------------------------------------------
// K_prep (64 CTAs x 256): CTA e owns expert e. No cross-CTA dependencies.
// Pads expert regions to 32 nodes. (R10/R12-proven, unchanged.)
// ---------------------------------------------------------------------------
__global__ __launch_bounds__(256, 2)
void prep_kernel(const float* __restrict__ W,
                 const long long* __restrict__ sel64) {
    const int tid = threadIdx.x;
    const int e   = blockIdx.x;

    __shared__ int bad;
    __shared__ int hist[NEXP];
    __shared__ int pads[NEXP];
    __shared__ int sc[NEXP];
    __shared__ int tc[256];

#pragma unroll
    for (int j = 0; j < 16; j++) {
        int i = e * 4096 + j * 256 + tid;
        float4 v = ((const float4*)W)[i];
        uint4 t;
        t.x = f2tf32(v.x); t.y = f2tf32(v.y);
        t.z = f2tf32(v.z); t.w = f2tf32(v.w);
        ((uint4*)g_Wr)[i] = t;
    }

    if (tid == 0) bad = 0;
    if (tid < NEXP) hist[tid] = 0;
    __syncthreads();
    if (tid < 64) {
        long long v = sel64[tid];
        if (v < 0 || v >= NEXP) atomicOr(&bad, 1);
    }
    __syncthreads();
    const int is64 = bad ? 0 : 1;

    int v[32];
    if (is64) {
        const longlong2* p = (const longlong2*)sel64 + tid * 16;
#pragma unroll
        for (int i = 0; i < 16; i++) {
            longlong2 q = p[i];
            v[2 * i]     = (int)q.x;
            v[2 * i + 1] = (int)q.y;
        }
    } else {
        const int4* p = (const int4*)sel64 + tid * 8;
#pragma unroll
        for (int i = 0; i < 8; i++) {
            int4 q = p[i];
            v[4 * i] = q.x; v[4 * i + 1] = q.y;
            v[4 * i + 2] = q.z; v[4 * i + 3] = q.w;
        }
    }

    int myc = 0;
#pragma unroll
    for (int i = 0; i < 32; i++) {
        atomicAdd(&hist[v[i]], 1);
        myc += (v[i] == e);
    }
    __syncthreads();

    if (tid < NEXP) {
        int pd = (hist[tid] + NODES_PER_CHUNK - 1) & ~(NODES_PER_CHUNK - 1);
        pads[tid] = pd;
        sc[tid] = pd;
    }
    __syncthreads();
#pragma unroll
    for (int d = 1; d < NEXP; d <<= 1) {
        int t = 0;
        if (tid < NEXP && tid >= d) t = sc[tid - d];
        __syncthreads();
        if (tid < NEXP) sc[tid] += t;
        __syncthreads();
    }
    const int offs_e = sc[e] - pads[e];
    const int cnt_e  = hist[e];
    const int pad_e  = pads[e];
    const int total  = sc[NEXP - 1];

    tc[tid] = myc;
    __syncthreads();
#pragma unroll
    for (int d = 1; d < 256; d <<= 1) {
        int t = 0;
        if (tid >= d) t = tc[tid - d];
        __syncthreads();
        tc[tid] += t;
        __syncthreads();
    }
    int w = offs_e + tc[tid] - myc;

#pragma unroll
    for (int i = 0; i < 32; i++)
        if (v[i] == e) g_sorted[w++] = tid * 32 + i;

    for (int i = cnt_e + tid; i < pad_e; i += 256)
        g_sorted[offs_e + i] = -1;

    for (int c = offs_e / NODES_PER_CHUNK + tid;
         c < (offs_e + pad_e) / NODES_PER_CHUNK; c += 256)
        g_chunk_expert[c] = e;
    if (e == 0)
        for (int c = total / NODES_PER_CHUNK + tid; c < MAX_CHK; c += 256)
            g_chunk_expert[c] = -1;
}

// ---------------------------------------------------------------------------
// K_gemm: 256 threads, 2 CTAs/SM. B resident (all K). A streams in 16-float
// tiles through a 4-deep ring (prefetch 3 phases ahead). 16 phases:
// sub0 k0..7, sub1 k0..7. Per phase: wait<2> -> sync -> issue A(j+3) ->
// compute (2 ksteps). Epilogue(sub0) at end of phase 7 overlaps sub1 loads.
// ---------------------------------------------------------------------------
extern __shared__ char smem[];

__global__ __launch_bounds__(256, 2)
void grouped_gemm_kernel(const float* __restrict__ x,
                         float* __restrict__ out) {
    const int e = g_chunk_expert[blockIdx.x];
    if (e < 0) return;

    int* snode = (int*)(smem + SMEM_NODE);
    const int tid  = threadIdx.x;
    const int lane = tid & 31;
    const int warp = tid >> 5;
    const int warp_m = (warp & 3) * 32;
    const int warp_n = (warp >> 2) * 64;

    if (tid < NODES_PER_CHUNK)
        snode[tid] = g_sorted[blockIdx.x * NODES_PER_CHUNK + tid];
    __syncthreads();

    const uint32_t sbase = smem_u32(smem);
    const float* Wre = g_Wr + (size_t)e * CH * CH;

    // --- A load geometry: 512 chunks of 16B per tile, 2 per thread ---
    // id = tid + i*256: row = id>>2 (0..127), cq = id&3
    const float* pA[2];
    uint32_t da[2];
    int rs[2];
#pragma unroll
    for (int i = 0; i < 2; i++) {
        int id  = tid + i * 256;
        int row = id >> 2;
        int cq  = id & 3;
        rs[i] = row >> 3;
        pA[i] = x + (size_t)(row & 7) * N_NODES * CH + cq * 4;
        da[i] = sbase + (uint32_t)A_OFF + (uint32_t)row * A_ROW + cq * 16;
    }

    // --- B load geometry: 1024 chunks per k-tile, 4 per thread ---
    const float* pB[4];
    uint32_t dbB[4];
#pragma unroll
    for (int i = 0; i < 4; i++) {
        int id  = tid + i * 256;
        int row = id >> 3;
        int cq  = id & 7;
        pB[i]  = Wre + (size_t)row * CH + cq * 4;
        dbB[i] = sbase + (uint32_t)row * B_ROW + cq * 16;
    }

    // --- ldmatrix base addresses ---
    uint32_t a_addr[2], b_addr[4];
    {
        int arow  = warp_m + (lane & 15);
        int abyte = (lane >> 4) * 16;
#pragma unroll
        for (int mt = 0; mt < 2; mt++)
            a_addr[mt] = sbase + (uint32_t)A_OFF
                       + (uint32_t)(arow + mt * 16) * A_ROW + abyte;

        int brow  = warp_n + ((lane >> 4) << 3) + (lane & 7);
        int bbyte = ((lane >> 3) & 1) * 16;
#pragma unroll
        for (int p = 0; p < 4; p++)
            b_addr[p] = sbase + (uint32_t)(brow + p * 16) * B_ROW + bbyte;
    }

    // issue A tile t (0..15): sub = t>>3, k16 = t&7, stage = t&3
    auto issue_A = [&](int t) {
        const int sub = t >> 3;
        const int k16 = t & 7;
        const uint32_t so = (uint32_t)(t & 3) * A_TILE;
#pragma unroll
        for (int i = 0; i < 2; i++) {
            int node = snode[sub * SUBN + rs[i]];
            int sz = (node >= 0) ? 16 : 0;
            int nn = (node < 0) ? 0 : node;
            cp16(da[i] + so, pA[i] + (size_t)nn * CH + k16 * 16, sz);
        }
        cp_commit();
    };

    float acc[2][8][4];
#pragma unroll
    for (int mt = 0; mt < 2; mt++)
#pragma unroll
        for (int nt = 0; nt < 8; nt++)
#pragma unroll
            for (int i = 0; i < 4; i++) acc[mt][nt][i] = 0.0f;

    const int g = lane >> 2;
    const int c = lane & 3;
    auto epilogue = [&](int sub) {
#pragma unroll
        for (int mt = 0; mt < 2; mt++) {
#pragma unroll
            for (int half = 0; half < 2; half++) {
                int r = warp_m + mt * 16 + g + half * 8;
                int node = snode[sub * SUBN + (r >> 3)];
                if (node < 0) continue;
                float* o = out + ((size_t)(r & 7) * N_NODES + node) * CH + warp_n;
#pragma unroll
                for (int nt = 0; nt < 8; nt++) {
                    float2 v2 = make_float2(acc[mt][nt][half * 2],
                                            acc[mt][nt][half * 2 + 1]);
                    *(float2*)(o + nt * 8 + c * 2) = v2;
                }
            }
        }
    };

    // --- prologue: resident B (one group; src stride 32 floats/k-tile)
    //     + A tiles 0..2 ---
#pragma unroll
    for (int kt = 0; kt < 4; kt++)
#pragma unroll
        for (int i = 0; i < 4; i++)
            cp16(dbB[i] + kt * B_KTILE, pB[i] + kt * 32, 16);
    cp_commit();
    issue_A(0);
    issue_A(1);
    issue_A(2);

    // --- 16 phases ---
#pragma unroll
    for (int j = 0; j < 16; j++) {
        if (j < 14)       cp_wait<2>();
        else if (j == 14) cp_wait<1>();
        else              cp_wait<0>();
        __syncthreads();

        if (j + 3 < 16) issue_A(j + 3);

        const uint32_t soA = (uint32_t)(j & 3) * A_TILE;
#pragma unroll
        for (int ks = 0; ks < 2; ks++) {
            const int gk = 2 * (j & 7) + ks;      // global 8-col kstep (0..15)
            const uint32_t soB = (uint32_t)(gk >> 2) * B_KTILE
                               + (uint32_t)(gk & 3) * 32;
            uint32_t a[2][4], b[4][4];
#pragma unroll
            for (int mt = 0; mt < 2; mt++)
                ldsm_x4(a[mt], a_addr[mt] + soA + ks * 32);
#pragma unroll
            for (int p = 0; p < 4; p++)
                ldsm_x4(b[p], b_addr[p] + soB);
#pragma unroll
            for (int mt = 0; mt < 2; mt++)
#pragma unroll
                for (int nt = 0; nt < 8; nt++)
                    mma_tf32(acc[mt][nt], a[mt], &b[nt >> 1][(nt & 1) * 2]);
        }

        if (j == 7) {
            epilogue(0);       // overlaps A8..A10 delivery
#pragma unroll
            for (int mt = 0; mt < 2; mt++)
#pragma unroll
                for (int nt = 0; nt < 8; nt++)
#pragma unroll
                    for (int i = 0; i < 4; i++) acc[mt][nt][i] = 0.0f;
        }
    }

    epilogue(1);
}

// ---------------------------------------------------------------------------
extern "C" void kernel_launch(void* const* d_in, const int* in_sizes, int n_in,
                              void* d_out, int out_size) {
    const float*     x   = (const float*)d_in[0];
    const long long* sel = (const long long*)d_in[1];
    const float*     W   = (const float*)d_in[2];
    float*           out = (float*)d_out;

    static bool attr_set = false;
    if (!attr_set) {
        cudaFuncSetAttribute(grouped_gemm_kernel,
                             cudaFuncAttributeMaxDynamicSharedMemorySize,
                             SMEM_TOTAL);
        attr_set = true;
    }

    prep_kernel<<<NEXP, 256>>>(W, sel);
    grouped_gemm_kernel<<<MAX_CHK, 256, SMEM_TOTAL>>>(x, out);
}

// round 16
// speedup vs baseline: 1.0556x; 1.0556x over previous
#include <cuda_runtime.h>
#include <cstdint>

// Problem constants
#define N_NODES  8192
#define CH       128
#define NEXP     64
#define NODES_PER_CHUNK 32              // nodes per GEMM CTA (2 subtiles of 16)
#define SUBN     16
#define MAX_PAD  10240                  // 8192 + 64*32
#define MAX_CHK  320                    // MAX_PAD / 32

// B resident in smem (all K=128, 32-float k-tile layout)
#define B_ROW     144                   // 32 words + 16B pad -> conflict-free ldsm
#define B_KTILE   (128 * B_ROW)         // 18432
#define B_BYTES   (4 * B_KTILE)         // 73728
#define SMEM_NODE B_BYTES
#define SMEM_TOTAL (SMEM_NODE + 128)

// Scratch
__device__ int   g_sorted[MAX_PAD];
__device__ int   g_chunk_expert[MAX_CHK];
__device__ float g_Wr[NEXP * CH * CH];  // tf32-rounded W

// ---------------------------------------------------------------------------
// helpers
// ---------------------------------------------------------------------------
__device__ __forceinline__ uint32_t smem_u32(const void* p) {
    uint32_t a;
    asm("{ .reg .u64 t; cvta.to.shared.u64 t, %1; cvt.u32.u64 %0, t; }"
        : "=r"(a) : "l"(p));
    return a;
}

__device__ __forceinline__ uint32_t f2tf32(float f) {
    uint32_t u;
    asm("cvt.rna.tf32.f32 %0, %1;" : "=r"(u) : "f"(f));
    return u;
}

__device__ __forceinline__ void cp16(uint32_t dst, const void* src, int sz) {
    asm volatile("cp.async.cg.shared.global [%0], [%1], 16, %2;"
                 :: "r"(dst), "l"(src), "r"(sz) : "memory");
}
__device__ __forceinline__ void cp_commit() {
    asm volatile("cp.async.commit_group;" ::: "memory");
}
template <int N>
__device__ __forceinline__ void cp_wait() {
    asm volatile("cp.async.wait_group %0;" :: "n"(N) : "memory");
}

__device__ __forceinline__ void ldsm_x4(uint32_t* r, uint32_t addr) {
    asm volatile("ldmatrix.sync.aligned.m8n8.x4.shared.b16 {%0,%1,%2,%3}, [%4];"
                 : "=r"(r[0]), "=r"(r[1]), "=r"(r[2]), "=r"(r[3])
                 : "r"(addr));
}

__device__ __forceinline__ void mma_tf32(float* d, const uint32_t* a, const uint32_t* b) {
    asm volatile(
        "mma.sync.aligned.m16n8k8.row.col.f32.tf32.tf32.f32 "
        "{%0,%1,%2,%3}, {%4,%5,%6,%7}, {%8,%9}, {%0,%1,%2,%3};\n"
        : "+f"(d[0]), "+f"(d[1]), "+f"(d[2]), "+f"(d[3])
        : "r"(a[0]), "r"(a[1]), "r"(a[2]), "r"(a[3]),
          "r"(b[0]), "r"(b[1]));
}

// ---------------------------------------------------------------------------
// K_prep (64 CTAs x 256): CTA e owns expert e. No cross-CTA dependencies.
// Pads expert regions to 32 nodes. (R10/R12-proven, unchanged.)
// ---------------------------------------------------------------------------
__global__ __launch_bounds__(256, 2)
void prep_kernel(const float* __restrict__ W,
                 const long long* __restrict__ sel64) {
    const int tid = threadIdx.x;
    const int e   = blockIdx.x;

    __shared__ int bad;
    __shared__ int hist[NEXP];
    __shared__ int pads[NEXP];
    __shared__ int sc[NEXP];
    __shared__ int tc[256];

#pragma unroll
    for (int j = 0; j < 16; j++) {
        int i = e * 4096 + j * 256 + tid;
        float4 v = ((const float4*)W)[i];
        uint4 t;
        t.x = f2tf32(v.x); t.y = f2tf32(v.y);
        t.z = f2tf32(v.z); t.w = f2tf32(v.w);
        ((uint4*)g_Wr)[i] = t;
    }

    if (tid == 0) bad = 0;
    if (tid < NEXP) hist[tid] = 0;
    __syncthreads();
    if (tid < 64) {
        long long v = sel64[tid];
        if (v < 0 || v >= NEXP) atomicOr(&bad, 1);
    }
    __syncthreads();
    const int is64 = bad ? 0 : 1;

    int v[32];
    if (is64) {
        const longlong2* p = (const longlong2*)sel64 + tid * 16;
#pragma unroll
        for (int i = 0; i < 16; i++) {
            longlong2 q = p[i];
            v[2 * i]     = (int)q.x;
            v[2 * i + 1] = (int)q.y;
        }
    } else {
        const int4* p = (const int4*)sel64 + tid * 8;
#pragma unroll
        for (int i = 0; i < 8; i++) {
            int4 q = p[i];
            v[4 * i] = q.x; v[4 * i + 1] = q.y;
            v[4 * i + 2] = q.z; v[4 * i + 3] = q.w;
        }
    }

    int myc = 0;
#pragma unroll
    for (int i = 0; i < 32; i++) {
        atomicAdd(&hist[v[i]], 1);
        myc += (v[i] == e);
    }
    __syncthreads();

    if (tid < NEXP) {
        int pd = (hist[tid] + NODES_PER_CHUNK - 1) & ~(NODES_PER_CHUNK - 1);
        pads[tid] = pd;
        sc[tid] = pd;
    }
    __syncthreads();
#pragma unroll
    for (int d = 1; d < NEXP; d <<= 1) {
        int t = 0;
        if (tid < NEXP && tid >= d) t = sc[tid - d];
        __syncthreads();
        if (tid < NEXP) sc[tid] += t;
        __syncthreads();
    }
    const int offs_e = sc[e] - pads[e];
    const int cnt_e  = hist[e];
    const int pad_e  = pads[e];
    const int total  = sc[NEXP - 1];

    tc[tid] = myc;
    __syncthreads();
#pragma unroll
    for (int d = 1; d < 256; d <<= 1) {
        int t = 0;
        if (tid >= d) t = tc[tid - d];
        __syncthreads();
        tc[tid] += t;
        __syncthreads();
    }
    int w = offs_e + tc[tid] - myc;

#pragma unroll
    for (int i = 0; i < 32; i++)
        if (v[i] == e) g_sorted[w++] = tid * 32 + i;

    for (int i = cnt_e + tid; i < pad_e; i += 256)
        g_sorted[offs_e + i] = -1;

    for (int c = offs_e / NODES_PER_CHUNK + tid;
         c < (offs_e + pad_e) / NODES_PER_CHUNK; c += 256)
        g_chunk_expert[c] = e;
    if (e == 0)
        for (int c = total / NODES_PER_CHUNK + tid; c < MAX_CHK; c += 256)
            g_chunk_expert[c] = -1;
}

// ---------------------------------------------------------------------------
// K_gemm: 256 threads, 2 CTAs/SM. B (W[e], all K) resident in smem, loaded
// once with a single barrier. A (x) loaded per-warp via LDG.32 DIRECTLY into
// mma fragments (no smem transit). Mainloop is barrier-free straight-line
// code per warp -> all latency hidden by 16 decoupled warps/SM.
// 8 warps in 4x2 grid, warp tile 32x64, 2 node-subtiles per CTA.
// ---------------------------------------------------------------------------
extern __shared__ char smem[];

__global__ __launch_bounds__(256, 2)
void grouped_gemm_kernel(const float* __restrict__ x,
                         float* __restrict__ out) {
    const int e = g_chunk_expert[blockIdx.x];
    if (e < 0) return;

    int* snode = (int*)(smem + SMEM_NODE);
    const int tid  = threadIdx.x;
    const int lane = tid & 31;
    const int warp = tid >> 5;
    const int warp_m = (warp & 3) * 32;
    const int warp_n = (warp >> 2) * 64;
    const int g = lane >> 2;
    const int c = lane & 3;

    if (tid < NODES_PER_CHUNK)
        snode[tid] = g_sorted[blockIdx.x * NODES_PER_CHUNK + tid];
    __syncthreads();

    const uint32_t sbase = smem_u32(smem);
    const float* Wre = g_Wr + (size_t)e * CH * CH;

    // --- B resident load: 4 chunks/thread per k-tile, 4 k-tiles ---
#pragma unroll
    for (int i = 0; i < 4; i++) {
        int id  = tid + i * 256;
        int row = id >> 3;
        int cq  = id & 7;
        const float* pB = Wre + (size_t)row * CH + cq * 4;
        uint32_t dB = sbase + (uint32_t)row * B_ROW + cq * 16;
#pragma unroll
        for (int kt = 0; kt < 4; kt++)
            cp16(dB + kt * B_KTILE, pB + kt * 32, 16);
    }
    cp_commit();

    // --- A fragment pointers: [sub][mt][half] -> row warp_m+mt*16+g+half*8 ---
    const float* pa[2][2][2];
#pragma unroll
    for (int sub = 0; sub < 2; sub++)
#pragma unroll
        for (int mt = 0; mt < 2; mt++)
#pragma unroll
            for (int h = 0; h < 2; h++) {
                int row  = warp_m + mt * 16 + g + h * 8;
                int node = snode[sub * SUBN + (row >> 3)];
                int nd   = (node < 0) ? 0 : node;   // pad rows: garbage, never stored
                pa[sub][mt][h] = x + (size_t)(row & 7) * N_NODES * CH
                                   + (size_t)nd * CH;
            }

    // --- B ldsm base addresses ---
    uint32_t b_addr[4];
    {
        int brow  = warp_n + ((lane >> 4) << 3) + (lane & 7);
        int bbyte = ((lane >> 3) & 1) * 16;
#pragma unroll
        for (int p = 0; p < 4; p++)
            b_addr[p] = sbase + (uint32_t)(brow + p * 16) * B_ROW + bbyte;
    }

    cp_wait<0>();
    __syncthreads();   // B ready; LAST barrier in the kernel

    float acc[2][8][4];

    auto epilogue = [&](int sub) {
#pragma unroll
        for (int mt = 0; mt < 2; mt++) {
#pragma unroll
            for (int half = 0; half < 2; half++) {
                int r = warp_m + mt * 16 + g + half * 8;
                int node = snode[sub * SUBN + (r >> 3)];
                if (node < 0) continue;
                float* o = out + ((size_t)(r & 7) * N_NODES + node) * CH + warp_n;
#pragma unroll
                for (int nt = 0; nt < 8; nt++) {
                    float2 v2 = make_float2(acc[mt][nt][half * 2],
                                            acc[mt][nt][half * 2 + 1]);
                    *(float2*)(o + nt * 8 + c * 2) = v2;
                }
            }
        }
    };

#pragma unroll
    for (int sub = 0; sub < 2; sub++) {
#pragma unroll
        for (int mt = 0; mt < 2; mt++)
#pragma unroll
            for (int nt = 0; nt < 8; nt++)
#pragma unroll
                for (int i = 0; i < 4; i++) acc[mt][nt][i] = 0.0f;

#pragma unroll 4
        for (int ks = 0; ks < 16; ks++) {
            // A fragments straight from global (L1-resident after 1st touch)
            uint32_t a[2][4];
#pragma unroll
            for (int mt = 0; mt < 2; mt++) {
                a[mt][0] = __float_as_uint(pa[sub][mt][0][ks * 8 + c]);
                a[mt][1] = __float_as_uint(pa[sub][mt][1][ks * 8 + c]);
                a[mt][2] = __float_as_uint(pa[sub][mt][0][ks * 8 + c + 4]);
                a[mt][3] = __float_as_uint(pa[sub][mt][1][ks * 8 + c + 4]);
            }
            // B fragments from resident smem
            const uint32_t soB = (uint32_t)(ks >> 2) * B_KTILE
                               + (uint32_t)(ks & 3) * 32;
            uint32_t b[4][4];
#pragma unroll
            for (int p = 0; p < 4; p++)
                ldsm_x4(b[p], b_addr[p] + soB);

#pragma unroll
            for (int mt = 0; mt < 2; mt++)
#pragma unroll
                for (int nt = 0; nt < 8; nt++)
                    mma_tf32(acc[mt][nt], a[mt], &b[nt >> 1][(nt & 1) * 2]);
        }

        epilogue(sub);
    }
}

// ---------------------------------------------------------------------------
extern "C" void kernel_launch(void* const* d_in, const int* in_sizes, int n_in,
                              void* d_out, int out_size) {
    const float*     x   = (const float*)d_in[0];
    const long long* sel = (const long long*)d_in[1];
    const float*     W   = (const float*)d_in[2];
    float*           out = (float*)d_out;

    static bool attr_set = false;
    if (!attr_set) {
        cudaFuncSetAttribute(grouped_gemm_kernel,
                             cudaFuncAttributeMaxDynamicSharedMemorySize,
                             SMEM_TOTAL);
        attr_set = true;
    }

    prep_kernel<<<NEXP, 256>>>(W, sel);
    grouped_gemm_kernel<<<MAX_CHK, 256, SMEM_TOTAL>>>(x, out);
}

// round 17
// speedup vs baseline: 1.5016x; 1.4226x over previous
#include <cuda_runtime.h>
#include <cstdint>

// Problem constants
#define N_NODES  8192
#define CH       128
#define NEXP     64
#define NODES_PER_CHUNK 32              // nodes per GEMM CTA (2 subtiles of 16)
#define SUBN     16
#define MAX_PAD  10240                  // 8192 + 64*32
#define MAX_CHK  320                    // MAX_PAD / 32

// B (resident, KT=32 layout) + A (2-stage double buffer)  [R13-proven]
#define ROW_BYTES 144                   // 32 words + 16B pad -> conflict-free ldsm
#define B_KTILE   (128 * ROW_BYTES)     // 18432
#define B_BYTES   (4 * B_KTILE)         // 73728
#define A_OFF     B_BYTES
#define A_STAGE   (128 * ROW_BYTES)     // 18432
#define SMEM_NODE (A_OFF + 2 * A_STAGE) // 110592
#define SMEM_TOTAL (SMEM_NODE + 128)

#define KT 32

// Scratch (no g_Wr anymore — W is rounded in smem inside the GEMM)
__device__ int g_sorted[MAX_PAD];
__device__ int g_chunk_expert[MAX_CHK];

// ---------------------------------------------------------------------------
// helpers
// ---------------------------------------------------------------------------
__device__ __forceinline__ uint32_t smem_u32(const void* p) {
    uint32_t a;
    asm("{ .reg .u64 t; cvta.to.shared.u64 t, %1; cvt.u32.u64 %0, t; }"
        : "=r"(a) : "l"(p));
    return a;
}

__device__ __forceinline__ uint32_t f2tf32(float f) {
    uint32_t u;
    asm("cvt.rna.tf32.f32 %0, %1;" : "=r"(u) : "f"(f));
    return u;
}

__device__ __forceinline__ void cp16(uint32_t dst, const void* src, int sz) {
    asm volatile("cp.async.cg.shared.global [%0], [%1], 16, %2;"
                 :: "r"(dst), "l"(src), "r"(sz) : "memory");
}
__device__ __forceinline__ void cp_commit() {
    asm volatile("cp.async.commit_group;" ::: "memory");
}
template <int N>
__device__ __forceinline__ void cp_wait() {
    asm volatile("cp.async.wait_group %0;" :: "n"(N) : "memory");
}

__device__ __forceinline__ void ldsm_x4(uint32_t* r, uint32_t addr) {
    asm volatile("ldmatrix.sync.aligned.m8n8.x4.shared.b16 {%0,%1,%2,%3}, [%4];"
                 : "=r"(r[0]), "=r"(r[1]), "=r"(r[2]), "=r"(r[3])
                 : "r"(addr));
}

__device__ __forceinline__ void mma_tf32(float* d, const uint32_t* a, const uint32_t* b) {
    asm volatile(
        "mma.sync.aligned.m16n8k8.row.col.f32.tf32.tf32.f32 "
        "{%0,%1,%2,%3}, {%4,%5,%6,%7}, {%8,%9}, {%0,%1,%2,%3};\n"
        : "+f"(d[0]), "+f"(d[1]), "+f"(d[2]), "+f"(d[3])
        : "r"(a[0]), "r"(a[1]), "r"(a[2]), "r"(a[3]),
          "r"(b[0]), "r"(b[1]));
}

// ---------------------------------------------------------------------------
// K_prep (64 CTAs x 256): CTA e owns expert e. No cross-CTA dependencies,
// NO W work anymore (W rounded in-smem by the GEMM). Hist+scan+scatter only.
// ---------------------------------------------------------------------------
__global__ __launch_bounds__(256, 2)
void prep_kernel(const long long* __restrict__ sel64) {
    const int tid = threadIdx.x;
    const int e   = blockIdx.x;

    __shared__ int bad;
    __shared__ int hist[NEXP];
    __shared__ int pads[NEXP];
    __shared__ int sc[NEXP];
    __shared__ int tc[256];

    // ---- dtype detect: 64 int64 words (512B; safe for min buffer) ----
    if (tid == 0) bad = 0;
    if (tid < NEXP) hist[tid] = 0;
    __syncthreads();
    if (tid < 64) {
        long long v = sel64[tid];
        if (v < 0 || v >= NEXP) atomicOr(&bad, 1);
    }
    __syncthreads();
    const int is64 = bad ? 0 : 1;

    // ---- load my 32 contiguous sel values ----
    int v[32];
    if (is64) {
        const longlong2* p = (const longlong2*)sel64 + tid * 16;
#pragma unroll
        for (int i = 0; i < 16; i++) {
            longlong2 q = p[i];
            v[2 * i]     = (int)q.x;
            v[2 * i + 1] = (int)q.y;
        }
    } else {
        const int4* p = (const int4*)sel64 + tid * 8;
#pragma unroll
        for (int i = 0; i < 8; i++) {
            int4 q = p[i];
            v[4 * i] = q.x; v[4 * i + 1] = q.y;
            v[4 * i + 2] = q.z; v[4 * i + 3] = q.w;
        }
    }

    int myc = 0;
#pragma unroll
    for (int i = 0; i < 32; i++) {
        atomicAdd(&hist[v[i]], 1);
        myc += (v[i] == e);
    }
    __syncthreads();

    if (tid < NEXP) {
        int pd = (hist[tid] + NODES_PER_CHUNK - 1) & ~(NODES_PER_CHUNK - 1);
        pads[tid] = pd;
        sc[tid] = pd;
    }
    __syncthreads();
#pragma unroll
    for (int d = 1; d < NEXP; d <<= 1) {
        int t = 0;
        if (tid < NEXP && tid >= d) t = sc[tid - d];
        __syncthreads();
        if (tid < NEXP) sc[tid] += t;
        __syncthreads();
    }
    const int offs_e = sc[e] - pads[e];
    const int cnt_e  = hist[e];
    const int pad_e  = pads[e];
    const int total  = sc[NEXP - 1];

    tc[tid] = myc;
    __syncthreads();
#pragma unroll
    for (int d = 1; d < 256; d <<= 1) {
        int t = 0;
        if (tid >= d) t = tc[tid - d];
        __syncthreads();
        tc[tid] += t;
        __syncthreads();
    }
    int w = offs_e + tc[tid] - myc;

#pragma unroll
    for (int i = 0; i < 32; i++)
        if (v[i] == e) g_sorted[w++] = tid * 32 + i;

    for (int i = cnt_e + tid; i < pad_e; i += 256)
        g_sorted[offs_e + i] = -1;

    for (int c = offs_e / NODES_PER_CHUNK + tid;
         c < (offs_e + pad_e) / NODES_PER_CHUNK; c += 256)
        g_chunk_expert[c] = e;
    if (e == 0)
        for (int c = total / NODES_PER_CHUNK + tid; c < MAX_CHK; c += 256)
            g_chunk_expert[c] = -1;
}

// ---------------------------------------------------------------------------
// K_gemm (R13-proven skeleton): 256 threads, 2 CTAs/SM. B (RAW W[e], all K)
// resident in smem, loaded once, then tf32-rounded IN-PLACE at phase 0
// (each thread converts exactly the chunks it cp.async'd). A streams raw
// through a 2-stage double-buffer. 8 phases: sub0 k0..3, sub1 k0..3.
// ---------------------------------------------------------------------------
extern __shared__ char smem[];

__global__ __launch_bounds__(256, 2)
void grouped_gemm_kernel(const float* __restrict__ x,
                         const float* __restrict__ W,
                         float* __restrict__ out) {
    const int e = g_chunk_expert[blockIdx.x];
    if (e < 0) return;

    int* snode = (int*)(smem + SMEM_NODE);
    const int tid  = threadIdx.x;
    const int lane = tid & 31;
    const int warp = tid >> 5;
    const int warp_m = (warp & 3) * 32;
    const int warp_n = (warp >> 2) * 64;

    if (tid < NODES_PER_CHUNK)
        snode[tid] = g_sorted[blockIdx.x * NODES_PER_CHUNK + tid];
    __syncthreads();

    const uint32_t sbase = smem_u32(smem);
    const float* Wre = W + (size_t)e * CH * CH;   // RAW W

    // --- per-thread load geometry: 4 16B-chunks per 128-row k-tile ---
    const float* pA[4];
    uint32_t da[4];
    uint32_t dbB[4];
    const float* pB[4];
    int rs[4];
#pragma unroll
    for (int i = 0; i < 4; i++) {
        int id  = tid + i * 256;
        int row = id >> 3;
        int cq  = id & 7;
        rs[i] = row >> 3;
        pA[i]  = x + (size_t)(row & 7) * N_NODES * CH + cq * 4;
        pB[i]  = Wre + (size_t)row * CH + cq * 4;
        da[i]  = sbase + (uint32_t)A_OFF + (uint32_t)row * ROW_BYTES + cq * 16;
        dbB[i] = sbase + (uint32_t)row * ROW_BYTES + cq * 16;
    }

    // --- ldmatrix base addresses ---
    uint32_t a_addr[2], b_addr[4];
    {
        int arow  = warp_m + (lane & 15);
        int abyte = (lane >> 4) * 16;
#pragma unroll
        for (int mt = 0; mt < 2; mt++)
            a_addr[mt] = sbase + (uint32_t)A_OFF
                       + (uint32_t)(arow + mt * 16) * ROW_BYTES + abyte;

        int brow  = warp_n + ((lane >> 4) << 3) + (lane & 7);
        int bbyte = ((lane >> 3) & 1) * 16;
#pragma unroll
        for (int p = 0; p < 4; p++)
            b_addr[p] = sbase + (uint32_t)(brow + p * 16) * ROW_BYTES + bbyte;
    }

    // issue A tile t (0..7): sub = t>>2, k = t&3, stage = t&1
    auto issue_A = [&](int t) {
        const int sub = t >> 2;
        const int k   = t & 3;
        const uint32_t so = (uint32_t)(t & 1) * A_STAGE;
#pragma unroll
        for (int i = 0; i < 4; i++) {
            int node = snode[sub * SUBN + rs[i]];
            int sz = (node >= 0) ? 16 : 0;
            int nn = (node < 0) ? 0 : node;
            cp16(da[i] + so, pA[i] + (size_t)nn * CH + k * KT, sz);
        }
        cp_commit();
    };

    float acc[2][8][4];
#pragma unroll
    for (int mt = 0; mt < 2; mt++)
#pragma unroll
        for (int nt = 0; nt < 8; nt++)
#pragma unroll
            for (int i = 0; i < 4; i++) acc[mt][nt][i] = 0.0f;

    const int g = lane >> 2;
    const int c = lane & 3;
    auto epilogue = [&](int sub) {
#pragma unroll
        for (int mt = 0; mt < 2; mt++) {
#pragma unroll
            for (int half = 0; half < 2; half++) {
                int r = warp_m + mt * 16 + g + half * 8;
                int node = snode[sub * SUBN + (r >> 3)];
                if (node < 0) continue;
                float* o = out + ((size_t)(r & 7) * N_NODES + node) * CH + warp_n;
#pragma unroll
                for (int nt = 0; nt < 8; nt++) {
                    float2 v2 = make_float2(acc[mt][nt][half * 2],
                                            acc[mt][nt][half * 2 + 1]);
                    *(float2*)(o + nt * 8 + c * 2) = v2;
                }
            }
        }
    };

    // --- prologue: resident B (raw, one group; src stride 32 floats/k-tile)
    //     + A tile 0 ---
#pragma unroll
    for (int kt = 0; kt < 4; kt++)
#pragma unroll
        for (int i = 0; i < 4; i++)
            cp16(dbB[i] + kt * B_KTILE, pB[i] + kt * KT, 16);
    cp_commit();
    issue_A(0);

    // --- 8 A-phases ---
#pragma unroll
    for (int j = 0; j < 8; j++) {
        cp_wait<0>();
        __syncthreads();

        if (j == 0) {
            // one-time in-place tf32 rounding of resident B (each thread
            // converts exactly the 16 chunks it cp.async'd)
#pragma unroll
            for (int kt = 0; kt < 4; kt++)
#pragma unroll
                for (int i = 0; i < 4; i++) {
                    uint32_t ad = dbB[i] + kt * B_KTILE;
                    uint4 vv = *(uint4*)(smem + (ad - sbase));
                    vv.x = f2tf32(__uint_as_float(vv.x));
                    vv.y = f2tf32(__uint_as_float(vv.y));
                    vv.z = f2tf32(__uint_as_float(vv.z));
                    vv.w = f2tf32(__uint_as_float(vv.w));
                    *(uint4*)(smem + (ad - sbase)) = vv;
                }
            __syncthreads();
        }

        if (j < 7) issue_A(j + 1);

        const uint32_t soA = (uint32_t)(j & 1) * A_STAGE;
        const uint32_t soB0 = (uint32_t)(j & 3) * B_KTILE;
#pragma unroll
        for (int ks = 0; ks < 4; ks++) {
            uint32_t a[2][4], b[4][4];
#pragma unroll
            for (int mt = 0; mt < 2; mt++)
                ldsm_x4(a[mt], a_addr[mt] + soA + ks * 32);
#pragma unroll
            for (int p = 0; p < 4; p++)
                ldsm_x4(b[p], b_addr[p] + soB0 + ks * 32);
#pragma unroll
            for (int mt = 0; mt < 2; mt++)
#pragma unroll
                for (int nt = 0; nt < 8; nt++)
                    mma_tf32(acc[mt][nt], a[mt], &b[nt >> 1][(nt & 1) * 2]);
        }

        if (j == 3) {
            epilogue(0);       // overlaps A4 delivery
#pragma unroll
            for (int mt = 0; mt < 2; mt++)
#pragma unroll
                for (int nt = 0; nt < 8; nt++)
#pragma unroll
                    for (int i = 0; i < 4; i++) acc[mt][nt][i] = 0.0f;
        }
    }

    epilogue(1);
}

// ---------------------------------------------------------------------------
extern "C" void kernel_launch(void* const* d_in, const int* in_sizes, int n_in,
                              void* d_out, int out_size) {
    const float*     x   = (const float*)d_in[0];
    const long long* sel = (const long long*)d_in[1];
    const float*     W   = (const float*)d_in[2];
    float*           out = (float*)d_out;

    static bool attr_set = false;
    if (!attr_set) {
        cudaFuncSetAttribute(grouped_gemm_kernel,
                             cudaFuncAttributeMaxDynamicSharedMemorySize,
                             SMEM_TOTAL);
        attr_set = true;
    }

    prep_kernel<<<NEXP, 256>>>(sel);
    grouped_gemm_kernel<<<MAX_CHK, 256, SMEM_TOTAL>>>(x, W, out);
}